// round 1
// baseline (speedup 1.0000x reference)
#include <cuda_runtime.h>
#include <cuda_bf16.h>
#include <cstdint>

// Problem constants
#define NB   8          // batch
#define NC   19         // channels
#define HW   512
#define NPIX (HW*HW)    // 262144 per image
#define NIMG 16         // 8 student + 8 teacher images
#define ITERS 25

// tile geometry for stage kernel
#define TS   32
#define AH   36         // TS + 2*halo(2)
#define AW   37         // padded row stride (conflict avoidance)

// ---------------- device scratch (allocation-free rule: __device__ globals) ----
__device__ float g_prob[NIMG * NPIX];   // [0..7]=student prob, [8..15]=teacher prob
__device__ float g_imA [NIMG * NPIX];
__device__ float g_imB [NIMG * NPIX];
__device__ float g_skel[NIMG * NPIX];
__device__ float g_partials[512];       // 256 blocks x 2 sums

// ---------------- kernel 1: softmax class-prob + teacher clip -------------------
__global__ void prob_kernel(const float* __restrict__ logits,
                            const float* __restrict__ mask,
                            const int* __restrict__ cidx) {
    int t = blockIdx.x * blockDim.x + threadIdx.x;
    if (t >= NB * NPIX) return;
    int b = t >> 18;            // / NPIX
    int p = t & (NPIX - 1);
    const float* lp = logits + (size_t)b * NC * NPIX + p;

    float m = -1e30f;
    #pragma unroll
    for (int c = 0; c < NC; c++) m = fmaxf(m, lp[(size_t)c * NPIX]);

    int ci = *cidx;
    float s = 0.f, target = 0.f;
    #pragma unroll
    for (int c = 0; c < NC; c++) {
        float e = __expf(lp[(size_t)c * NPIX] - m);
        s += e;
        if (c == ci) target = e;
    }
    float pr = target / s;
    g_prob[t] = fminf(fmaxf(pr, 0.f), 1.f);                 // student prob (clip no-op but matches ref)
    g_prob[NB * NPIX + t] = fminf(fmaxf(mask[t], 0.f), 1.f); // teacher prob
}

// ---------------- kernel 2: one soft-skeleton stage ------------------------------
// e = erode(im); d = dilate(e); delta = relu(im - d);
// skel = init ? delta : skel + relu(delta - skel*delta);  im_out = e
__global__ void stage_kernel(int src, int dst, int init) {
    __shared__ float A[AH * AW];
    __shared__ float Bsh[AH * AW];

    const float* im_in  = (src == 0) ? g_prob : (src == 1 ? g_imA : g_imB);
    float*       im_out = (dst == 1) ? g_imA : g_imB;

    int img = blockIdx.z;
    int ty0 = blockIdx.y * TS, tx0 = blockIdx.x * TS;
    const float* base = im_in + img * NPIX;
    int tid = threadIdx.x;   // 256 threads

    // load im tile + halo2; out-of-image -> +inf (erode padding)
    for (int idx = tid; idx < AH * AH; idx += 256) {
        int ly = idx / AH, lx = idx % AH;
        int gy = ty0 + ly - 2, gx = tx0 + lx - 2;
        float v = 1e30f;
        if (gy >= 0 && gy < HW && gx >= 0 && gx < HW) v = base[gy * HW + gx];
        A[ly * AW + lx] = v;
    }
    __syncthreads();

    // stash this thread's 4 output-center im values before A gets overwritten
    float cent[4];
    #pragma unroll
    for (int k = 0; k < 4; k++) {
        int p = tid + k * 256; int ly = p >> 5, lx = p & 31;
        cent[k] = A[(ly + 2) * AW + lx + 2];
    }

    // vmin -> Bsh, rows 1..34, cols 0..35
    for (int idx = tid; idx < 34 * 36; idx += 256) {
        int ly = idx / 36 + 1, lx = idx % 36;
        Bsh[ly * AW + lx] = fminf(fminf(A[(ly - 1) * AW + lx], A[ly * AW + lx]),
                                  A[(ly + 1) * AW + lx]);
    }
    __syncthreads();

    // hmin -> E stored back into A, rows/cols 1..34; out-of-image e = -inf (dilate padding)
    for (int idx = tid; idx < 34 * 34; idx += 256) {
        int ly = idx / 34 + 1, lx = idx % 34 + 1;
        int gy = ty0 + ly - 2, gx = tx0 + lx - 2;
        float v;
        if (gy >= 0 && gy < HW && gx >= 0 && gx < HW)
            v = fminf(fminf(Bsh[ly * AW + lx - 1], Bsh[ly * AW + lx]), Bsh[ly * AW + lx + 1]);
        else
            v = -1e30f;
        A[ly * AW + lx] = v;
    }
    __syncthreads();

    // vmax of E -> Bsh, rows 2..33, cols 1..34
    for (int idx = tid; idx < 32 * 34; idx += 256) {
        int ly = idx / 34 + 2, lx = idx % 34 + 1;
        Bsh[ly * AW + lx] = fmaxf(fmaxf(A[(ly - 1) * AW + lx], A[ly * AW + lx]),
                                  A[(ly + 1) * AW + lx]);
    }
    __syncthreads();

    // outputs: d = hmax(vmax), delta, skel update, im_out = e
    float* skelp = g_skel + img * NPIX;
    float* outp  = im_out + img * NPIX;
    #pragma unroll
    for (int k = 0; k < 4; k++) {
        int p = tid + k * 256; int ly = p >> 5, lx = p & 31;
        int sy = ly + 2, sx = lx + 2;
        float d = fmaxf(fmaxf(Bsh[sy * AW + sx - 1], Bsh[sy * AW + sx]),
                        Bsh[sy * AW + sx + 1]);
        float delta = fmaxf(cent[k] - d, 0.0f);
        int g = (ty0 + ly) * HW + (tx0 + lx);
        float sk;
        if (init) sk = delta;
        else { sk = skelp[g]; sk = sk + fmaxf(delta - sk * delta, 0.0f); }
        skelp[g] = sk;
        outp[g]  = A[sy * AW + sx];   // e at center
    }
}

// ---------------- kernel 3: deterministic block-partial reduction ----------------
// block (img, chunk): sums skel[img]*prob[img^8] and skel[img] over 16384 px
__global__ void reduce_kernel() {
    int img   = blockIdx.x >> 4;
    int chunk = blockIdx.x & 15;
    int pair  = img ^ 8;
    const float* sk = g_skel + img  * NPIX + chunk * 16384;
    const float* pp = g_prob + pair * NPIX + chunk * 16384;

    float s0 = 0.f, s1 = 0.f;
    for (int i = threadIdx.x; i < 16384; i += 256) {
        float s = sk[i];
        s0 += s * pp[i];
        s1 += s;
    }
    #pragma unroll
    for (int o = 16; o > 0; o >>= 1) {
        s0 += __shfl_down_sync(0xFFFFFFFFu, s0, o);
        s1 += __shfl_down_sync(0xFFFFFFFFu, s1, o);
    }
    __shared__ float sh[64];
    int w = threadIdx.x >> 5;
    if ((threadIdx.x & 31) == 0) { sh[w] = s0; sh[32 + w] = s1; }
    __syncthreads();
    if (threadIdx.x == 0) {
        float a = 0.f, b = 0.f;
        #pragma unroll
        for (int i = 0; i < 8; i++) { a += sh[i]; b += sh[32 + i]; }
        g_partials[blockIdx.x * 2]     = a;
        g_partials[blockIdx.x * 2 + 1] = b;
    }
}

// ---------------- kernel 4: final clDice scalar ----------------------------------
__global__ void final_kernel(float* __restrict__ out) {
    const float EPSV = 1e-6f;
    float acc = 0.f;
    for (int b = 0; b < NB; b++) {
        float sp = 0.f, ss = 0.f, tp = 0.f, ts = 0.f;
        for (int c = 0; c < 16; c++) {
            sp += g_partials[(b * 16 + c) * 2];
            ss += g_partials[(b * 16 + c) * 2 + 1];
            tp += g_partials[((b + 8) * 16 + c) * 2];
            ts += g_partials[((b + 8) * 16 + c) * 2 + 1];
        }
        float tprec = (sp + EPSV) / (ss + EPSV);
        float tsens = (tp + EPSV) / (ts + EPSV);
        float cl = (2.f * tprec * tsens + EPSV) / (tprec + tsens + EPSV);
        acc += 1.f - cl;
    }
    out[0] = acc * 0.125f;
}

// ---------------- launch ----------------------------------------------------------
extern "C" void kernel_launch(void* const* d_in, const int* in_sizes, int n_in,
                              void* d_out, int out_size) {
    const float* logits = (const float*)d_in[0];
    const float* mask   = (const float*)d_in[1];
    const int*   cidx   = (const int*)d_in[2];
    float* out = (float*)d_out;

    prob_kernel<<<(NB * NPIX + 255) / 256, 256>>>(logits, mask, cidx);

    dim3 grid(HW / TS, HW / TS, NIMG);   // 16 x 16 x 16
    stage_kernel<<<grid, 256>>>(0, 1, 1);   // stage 0: src=prob, dst=A, init skel
    int src = 1;
    for (int t = 1; t < ITERS; t++) {
        int dst = (src == 1) ? 2 : 1;
        stage_kernel<<<grid, 256>>>(src, dst, 0);
        src = dst;
    }

    reduce_kernel<<<256, 256>>>();
    final_kernel<<<1, 1>>>(out);
}

// round 2
// speedup vs baseline: 2.5279x; 2.5279x over previous
#include <cuda_runtime.h>
#include <cuda_bf16.h>
#include <cstdint>

#define NB   8
#define NC   19
#define HW   512
#define NPIX (HW*HW)
#define NIMG 16
#define ITERS 25
#define BIG  1e30f

// per-warp tile geometry
#define OUTW 120            // output cols per warp (stripe)
#define NSX  5              // ceil(512/120)
#define ROWS 16             // output rows per warp
#define NSY  (HW/ROWS)      // 32
#define WPI  (NSX*NSY)      // 160 warps per image

__device__ float g_prob[NIMG * NPIX];
__device__ float g_imA [NIMG * NPIX];
__device__ float g_imB [NIMG * NPIX];
__device__ float g_skel[NIMG * NPIX];
__device__ float g_partials[512];

// ---------------- kernel 1: softmax class-prob + teacher clip -------------------
__global__ void prob_kernel(const float* __restrict__ logits,
                            const float* __restrict__ mask,
                            const int* __restrict__ cidx) {
    int t = blockIdx.x * blockDim.x + threadIdx.x;
    if (t >= NB * NPIX) return;
    int b = t >> 18;
    int p = t & (NPIX - 1);
    const float* lp = logits + (size_t)b * NC * NPIX + p;

    float m = -1e30f;
    #pragma unroll
    for (int c = 0; c < NC; c++) m = fmaxf(m, lp[(size_t)c * NPIX]);

    int ci = *cidx;
    float s = 0.f, target = 0.f;
    #pragma unroll
    for (int c = 0; c < NC; c++) {
        float e = __expf(lp[(size_t)c * NPIX] - m);
        s += e;
        if (c == ci) target = e;
    }
    float pr = target / s;
    g_prob[t] = fminf(fmaxf(pr, 0.f), 1.f);
    g_prob[NB * NPIX + t] = fminf(fmaxf(mask[t], 0.f), 1.f);
}

// ---------------- register/shuffle morphology helpers -----------------------------
__device__ __forceinline__ float4 ldrow(const float* __restrict__ b, int q, int gx, bool ok) {
    if (ok && (unsigned)q < HW) return *(const float4*)(b + q * HW + gx);
    float4 r; r.x = r.y = r.z = r.w = BIG; return r;
}

// E = hmin(vmin(im)) for one row; -BIG outside image (dilate padding for next op)
__device__ __forceinline__ float4 Erow(float4 a, float4 b, float4 c, bool colIn, int q) {
    float4 e;
    if ((unsigned)q >= HW) { e.x = e.y = e.z = e.w = -BIG; return e; }  // warp-uniform
    float4 v;
    v.x = fminf(fminf(a.x, b.x), c.x);
    v.y = fminf(fminf(a.y, b.y), c.y);
    v.z = fminf(fminf(a.z, b.z), c.z);
    v.w = fminf(fminf(a.w, b.w), c.w);
    float vl = __shfl_up_sync(0xFFFFFFFFu, v.w, 1);
    float vr = __shfl_down_sync(0xFFFFFFFFu, v.x, 1);
    float m01 = fminf(v.x, v.y), m12 = fminf(v.y, v.z), m23 = fminf(v.z, v.w);
    e.x = fminf(vl, m01);
    e.y = fminf(m01, v.z);
    e.z = fminf(m12, v.w);
    e.w = fminf(m23, vr);
    if (!colIn) { e.x = e.y = e.z = e.w = -BIG; }
    return e;
}

// d = hmax(vmax(E)) for one row
__device__ __forceinline__ float4 Drow(float4 a, float4 b, float4 c) {
    float4 t;
    t.x = fmaxf(fmaxf(a.x, b.x), c.x);
    t.y = fmaxf(fmaxf(a.y, b.y), c.y);
    t.z = fmaxf(fmaxf(a.z, b.z), c.z);
    t.w = fmaxf(fmaxf(a.w, b.w), c.w);
    float tl = __shfl_up_sync(0xFFFFFFFFu, t.w, 1);
    float tr = __shfl_down_sync(0xFFFFFFFFu, t.x, 1);
    float M01 = fmaxf(t.x, t.y), M12 = fmaxf(t.y, t.z), M23 = fmaxf(t.z, t.w);
    float4 d;
    d.x = fmaxf(tl, M01);
    d.y = fmaxf(M01, t.z);
    d.z = fmaxf(M12, t.w);
    d.w = fmaxf(M23, tr);
    return d;
}

// ---------------- kernel 2: one soft-skeleton stage (register rolling window) -----
// flags: bit0 = init skel, bit1 = skip e-store (last stage)
__global__ void __launch_bounds__(256) stage_kernel(int srcsel, int dstsel, int flags) {
    int w    = (blockIdx.x << 3) + (threadIdx.x >> 5);
    int lane = threadIdx.x & 31;
    int img  = w / WPI;
    int rem  = w - img * WPI;
    int sx   = rem >> 5;        // 0..4
    int sy   = rem & 31;        // 0..31
    int x0   = sx * OUTW;
    int r0   = sy * ROWS;
    int gx   = x0 - 4 + (lane << 2);

    bool colIn = (gx >= 0) && (gx < HW);
    bool stl   = (gx >= x0) && (gx < x0 + OUTW) && (gx < HW);

    const float* __restrict__ base =
        ((srcsel == 0) ? g_prob : (srcsel == 1 ? g_imA : g_imB)) + img * NPIX;
    float* __restrict__ outp = ((dstsel == 1) ? g_imA : g_imB) + img * NPIX;
    float* __restrict__ skp  = g_skel + img * NPIX;

    float4 im[3];
    im[0] = ldrow(base, r0 - 2, gx, colIn);
    im[1] = ldrow(base, r0 - 1, gx, colIn);
    im[2] = ldrow(base, r0,     gx, colIn);
    float4 Eprev = Erow(im[0], im[1], im[2], colIn, r0 - 1);
    im[0] = ldrow(base, r0 + 1, gx, colIn);
    float4 Ecur  = Erow(im[1], im[2], im[0], colIn, r0);

    bool init  = (flags & 1) != 0;
    bool skipE = (flags & 2) != 0;

    #pragma unroll
    for (int i = 0; i < ROWS; i++) {
        int r = r0 + i;
        im[(1 + i) % 3] = ldrow(base, r + 2, gx, colIn);
        // E(r+1) from im rows r, r+1, r+2
        float4 En = Erow(im[(2 + i) % 3], im[i % 3], im[(1 + i) % 3], colIn, r + 1);
        float4 dd = Drow(Eprev, Ecur, En);
        float4 ic = im[(2 + i) % 3];   // im row r
        float4 delta;
        delta.x = fmaxf(ic.x - dd.x, 0.f);
        delta.y = fmaxf(ic.y - dd.y, 0.f);
        delta.z = fmaxf(ic.z - dd.z, 0.f);
        delta.w = fmaxf(ic.w - dd.w, 0.f);

        if (stl) {
            int o = r * HW + gx;
            if (!skipE) *(float4*)(outp + o) = Ecur;   // im_out = erode(im) = E(r)
            if (init) {
                *(float4*)(skp + o) = delta;
            } else {
                float4 s = *(const float4*)(skp + o);
                s.x += fmaxf(delta.x - s.x * delta.x, 0.f);
                s.y += fmaxf(delta.y - s.y * delta.y, 0.f);
                s.z += fmaxf(delta.z - s.z * delta.z, 0.f);
                s.w += fmaxf(delta.w - s.w * delta.w, 0.f);
                *(float4*)(skp + o) = s;
            }
        }
        Eprev = Ecur; Ecur = En;
    }
}

// ---------------- kernel 3: deterministic block-partial reduction ----------------
__global__ void reduce_kernel() {
    int img   = blockIdx.x >> 4;
    int chunk = blockIdx.x & 15;
    int pair  = img ^ 8;
    const float* sk = g_skel + img  * NPIX + chunk * 16384;
    const float* pp = g_prob + pair * NPIX + chunk * 16384;

    float s0 = 0.f, s1 = 0.f;
    for (int i = threadIdx.x; i < 16384; i += 256) {
        float s = sk[i];
        s0 += s * pp[i];
        s1 += s;
    }
    #pragma unroll
    for (int o = 16; o > 0; o >>= 1) {
        s0 += __shfl_down_sync(0xFFFFFFFFu, s0, o);
        s1 += __shfl_down_sync(0xFFFFFFFFu, s1, o);
    }
    __shared__ float sh[64];
    int wp = threadIdx.x >> 5;
    if ((threadIdx.x & 31) == 0) { sh[wp] = s0; sh[32 + wp] = s1; }
    __syncthreads();
    if (threadIdx.x == 0) {
        float a = 0.f, b = 0.f;
        #pragma unroll
        for (int i = 0; i < 8; i++) { a += sh[i]; b += sh[32 + i]; }
        g_partials[blockIdx.x * 2]     = a;
        g_partials[blockIdx.x * 2 + 1] = b;
    }
}

// ---------------- kernel 4: final clDice scalar ----------------------------------
__global__ void final_kernel(float* __restrict__ out) {
    const float EPSV = 1e-6f;
    float acc = 0.f;
    for (int b = 0; b < NB; b++) {
        float sp = 0.f, ss = 0.f, tp = 0.f, ts = 0.f;
        for (int c = 0; c < 16; c++) {
            sp += g_partials[(b * 16 + c) * 2];
            ss += g_partials[(b * 16 + c) * 2 + 1];
            tp += g_partials[((b + 8) * 16 + c) * 2];
            ts += g_partials[((b + 8) * 16 + c) * 2 + 1];
        }
        float tprec = (sp + EPSV) / (ss + EPSV);
        float tsens = (tp + EPSV) / (ts + EPSV);
        float cl = (2.f * tprec * tsens + EPSV) / (tprec + tsens + EPSV);
        acc += 1.f - cl;
    }
    out[0] = acc * 0.125f;
}

// ---------------- launch ----------------------------------------------------------
extern "C" void kernel_launch(void* const* d_in, const int* in_sizes, int n_in,
                              void* d_out, int out_size) {
    const float* logits = (const float*)d_in[0];
    const float* mask   = (const float*)d_in[1];
    const int*   cidx   = (const int*)d_in[2];
    float* out = (float*)d_out;

    prob_kernel<<<(NB * NPIX + 255) / 256, 256>>>(logits, mask, cidx);

    int nblocks = (NIMG * WPI) / 8;   // 320 blocks of 8 warps
    stage_kernel<<<nblocks, 256>>>(0, 1, 1);        // stage 0: src=prob, init skel
    int src = 1;
    for (int t = 1; t < ITERS; t++) {
        int dst = (src == 1) ? 2 : 1;
        int flags = (t == ITERS - 1) ? 2 : 0;       // last stage: skip e-store
        stage_kernel<<<nblocks, 256>>>(src, dst, flags);
        src = dst;
    }

    reduce_kernel<<<256, 256>>>();
    final_kernel<<<1, 1>>>(out);
}

// round 3
// speedup vs baseline: 3.2319x; 1.2785x over previous
#include <cuda_runtime.h>
#include <cuda_bf16.h>
#include <cstdint>

#define NB   8
#define NC   19
#define HW   512
#define NPIX (HW*HW)
#define NIMG 16
#define ITERS 25
#define BIG  1e30f

// per-warp tile geometry
#define OUTW 120            // output cols per warp stripe
#define NSX  5              // stripes in x
#define ROWS 8              // output rows per warp
#define NSY  (HW/ROWS)      // 64
#define WPI  (NSX*NSY)      // 320 warps per image

__device__ float g_prob[NIMG * NPIX];
__device__ float g_imA [NIMG * NPIX];
__device__ float g_imB [NIMG * NPIX];
__device__ float g_skel[NIMG * NPIX];
__device__ float g_partials[512];

// ---------------- kernel 1: softmax class-prob + teacher clip (float4) ----------
__global__ void prob_kernel(const float* __restrict__ logits,
                            const float* __restrict__ mask,
                            const int* __restrict__ cidx) {
    int t = blockIdx.x * blockDim.x + threadIdx.x;      // one thread = 4 px
    if (t >= NB * NPIX / 4) return;
    int b = t >> 16;                 // / (NPIX/4)
    int p = (t & 65535) << 2;        // pixel within image
    const float* lp = logits + (size_t)b * NC * NPIX + p;

    float4 v[NC];
    #pragma unroll
    for (int c = 0; c < NC; c++) v[c] = *(const float4*)(lp + (size_t)c * NPIX);

    float4 m = v[0];
    #pragma unroll
    for (int c = 1; c < NC; c++) {
        m.x = fmaxf(m.x, v[c].x); m.y = fmaxf(m.y, v[c].y);
        m.z = fmaxf(m.z, v[c].z); m.w = fmaxf(m.w, v[c].w);
    }
    int ci = *cidx;
    float4 s = {0,0,0,0}, tg = {0,0,0,0};
    #pragma unroll
    for (int c = 0; c < NC; c++) {
        float4 e;
        e.x = __expf(v[c].x - m.x); e.y = __expf(v[c].y - m.y);
        e.z = __expf(v[c].z - m.z); e.w = __expf(v[c].w - m.w);
        s.x += e.x; s.y += e.y; s.z += e.z; s.w += e.w;
        if (c == ci) tg = e;
    }
    float4 pr;
    pr.x = fminf(fmaxf(tg.x / s.x, 0.f), 1.f);
    pr.y = fminf(fmaxf(tg.y / s.y, 0.f), 1.f);
    pr.z = fminf(fmaxf(tg.z / s.z, 0.f), 1.f);
    pr.w = fminf(fmaxf(tg.w / s.w, 0.f), 1.f);
    *(float4*)(g_prob + b * NPIX + p) = pr;

    float4 mk = *(const float4*)(mask + b * NPIX + p);
    mk.x = fminf(fmaxf(mk.x, 0.f), 1.f);
    mk.y = fminf(fmaxf(mk.y, 0.f), 1.f);
    mk.z = fminf(fmaxf(mk.z, 0.f), 1.f);
    mk.w = fminf(fmaxf(mk.w, 0.f), 1.f);
    *(float4*)(g_prob + (NB + b) * NPIX + p) = mk;
}

// ---------------- register/shuffle morphology helpers -----------------------------
__device__ __forceinline__ float4 ldrow(const float* __restrict__ b, int q, int gx, bool ok) {
    if (ok && (unsigned)q < HW) return *(const float4*)(b + q * HW + gx);
    float4 r; r.x = r.y = r.z = r.w = BIG; return r;
}

// E = hmin(vmin(im)) for one row; -BIG outside image (dilate padding)
__device__ __forceinline__ float4 Erow(float4 a, float4 b, float4 c, bool colIn, int q) {
    float4 e;
    if ((unsigned)q >= HW) { e.x = e.y = e.z = e.w = -BIG; return e; }  // warp-uniform
    float4 v;
    v.x = fminf(fminf(a.x, b.x), c.x);
    v.y = fminf(fminf(a.y, b.y), c.y);
    v.z = fminf(fminf(a.z, b.z), c.z);
    v.w = fminf(fminf(a.w, b.w), c.w);
    float vl = __shfl_up_sync(0xFFFFFFFFu, v.w, 1);
    float vr = __shfl_down_sync(0xFFFFFFFFu, v.x, 1);
    float m01 = fminf(v.x, v.y), m12 = fminf(v.y, v.z), m23 = fminf(v.z, v.w);
    e.x = fminf(vl, m01);
    e.y = fminf(m01, v.z);
    e.z = fminf(m12, v.w);
    e.w = fminf(m23, vr);
    if (!colIn) { e.x = e.y = e.z = e.w = -BIG; }
    return e;
}

__device__ __forceinline__ float4 Drow(float4 a, float4 b, float4 c) {
    float4 t;
    t.x = fmaxf(fmaxf(a.x, b.x), c.x);
    t.y = fmaxf(fmaxf(a.y, b.y), c.y);
    t.z = fmaxf(fmaxf(a.z, b.z), c.z);
    t.w = fmaxf(fmaxf(a.w, b.w), c.w);
    float tl = __shfl_up_sync(0xFFFFFFFFu, t.w, 1);
    float tr = __shfl_down_sync(0xFFFFFFFFu, t.x, 1);
    float M01 = fmaxf(t.x, t.y), M12 = fmaxf(t.y, t.z), M23 = fmaxf(t.z, t.w);
    float4 d;
    d.x = fmaxf(tl, M01);
    d.y = fmaxf(M01, t.z);
    d.z = fmaxf(M12, t.w);
    d.w = fmaxf(M23, tr);
    return d;
}

// ---------------- kernel 2: one stage, 6-row ring + prefetch distance 2 -----------
// flags: bit0 = init skel, bit1 = skip e-store (last stage)
__global__ void __launch_bounds__(256) stage_kernel(int srcsel, int dstsel, int flags) {
    int w    = (blockIdx.x << 3) + (threadIdx.x >> 5);
    int lane = threadIdx.x & 31;
    int img  = w / WPI;
    int rem  = w - img * WPI;
    int sx   = rem / NSY;       // 0..4
    int sy   = rem - sx * NSY;  // 0..63
    int x0   = sx * OUTW;
    int r0   = sy * ROWS;
    int gx   = x0 - 4 + (lane << 2);

    bool colIn = (gx >= 0) && (gx < HW);
    bool stl   = (gx >= x0) && (gx < x0 + OUTW) && (gx < HW);

    const float* __restrict__ base =
        ((srcsel == 0) ? g_prob : (srcsel == 1 ? g_imA : g_imB)) + img * NPIX;
    float* __restrict__ outp = ((dstsel == 1) ? g_imA : g_imB) + img * NPIX;
    float* __restrict__ skp  = g_skel + img * NPIX;

    bool init  = (flags & 1) != 0;
    bool skipE = (flags & 2) != 0;

    // ring slot j holds image row (r0 - 2 + j) initially; at iter i,
    // slot i%6 is overwritten with row r0+4+i (prefetch distance 2).
    float4 ring[6];
    #pragma unroll
    for (int j = 0; j < 6; j++) ring[j] = ldrow(base, r0 - 2 + j, gx, colIn);

    float4 Eprev = Erow(ring[0], ring[1], ring[2], colIn, r0 - 1);
    float4 Ecur  = Erow(ring[1], ring[2], ring[3], colIn, r0);

    #pragma unroll
    for (int i = 0; i < ROWS; i++) {
        int r = r0 + i;
        // prefetch row r+4 (consumed at iter i+2)
        ring[i % 6] = ldrow(base, r + 4, gx, colIn);
        // prefetch skel row (independent of compute chain)
        float4 s;
        int o = r * HW + gx;
        if (stl && !init) s = *(const float4*)(skp + o);

        // En = E(r+1) from rows r, r+1, r+2 -> slots (i+2),(i+3),(i+4) mod 6
        float4 En = Erow(ring[(i + 2) % 6], ring[(i + 3) % 6], ring[(i + 4) % 6],
                         colIn, r + 1);
        float4 dd = Drow(Eprev, Ecur, En);
        float4 ic = ring[(i + 2) % 6];   // im row r
        float4 delta;
        delta.x = fmaxf(ic.x - dd.x, 0.f);
        delta.y = fmaxf(ic.y - dd.y, 0.f);
        delta.z = fmaxf(ic.z - dd.z, 0.f);
        delta.w = fmaxf(ic.w - dd.w, 0.f);

        if (stl) {
            if (!skipE) *(float4*)(outp + o) = Ecur;   // im_out = erode(im)
            if (init) {
                *(float4*)(skp + o) = delta;
            } else {
                s.x += fmaxf(delta.x - s.x * delta.x, 0.f);
                s.y += fmaxf(delta.y - s.y * delta.y, 0.f);
                s.z += fmaxf(delta.z - s.z * delta.z, 0.f);
                s.w += fmaxf(delta.w - s.w * delta.w, 0.f);
                *(float4*)(skp + o) = s;
            }
        }
        Eprev = Ecur; Ecur = En;
    }
}

// ---------------- kernel 3: deterministic block-partial reduction ----------------
__global__ void reduce_kernel() {
    int img   = blockIdx.x >> 4;
    int chunk = blockIdx.x & 15;
    int pair  = img ^ 8;
    const float* sk = g_skel + img  * NPIX + chunk * 16384;
    const float* pp = g_prob + pair * NPIX + chunk * 16384;

    float s0 = 0.f, s1 = 0.f;
    for (int i = threadIdx.x * 4; i < 16384; i += 1024) {
        float4 a = *(const float4*)(sk + i);
        float4 b = *(const float4*)(pp + i);
        s0 += a.x * b.x + a.y * b.y + a.z * b.z + a.w * b.w;
        s1 += a.x + a.y + a.z + a.w;
    }
    #pragma unroll
    for (int o = 16; o > 0; o >>= 1) {
        s0 += __shfl_down_sync(0xFFFFFFFFu, s0, o);
        s1 += __shfl_down_sync(0xFFFFFFFFu, s1, o);
    }
    __shared__ float sh[64];
    int wp = threadIdx.x >> 5;
    if ((threadIdx.x & 31) == 0) { sh[wp] = s0; sh[32 + wp] = s1; }
    __syncthreads();
    if (threadIdx.x == 0) {
        float a = 0.f, b = 0.f;
        #pragma unroll
        for (int i = 0; i < 8; i++) { a += sh[i]; b += sh[32 + i]; }
        g_partials[blockIdx.x * 2]     = a;
        g_partials[blockIdx.x * 2 + 1] = b;
    }
}

// ---------------- kernel 4: final clDice scalar ----------------------------------
__global__ void final_kernel(float* __restrict__ out) {
    const float EPSV = 1e-6f;
    float acc = 0.f;
    for (int b = 0; b < NB; b++) {
        float sp = 0.f, ss = 0.f, tp = 0.f, ts = 0.f;
        for (int c = 0; c < 16; c++) {
            sp += g_partials[(b * 16 + c) * 2];
            ss += g_partials[(b * 16 + c) * 2 + 1];
            tp += g_partials[((b + 8) * 16 + c) * 2];
            ts += g_partials[((b + 8) * 16 + c) * 2 + 1];
        }
        float tprec = (sp + EPSV) / (ss + EPSV);
        float tsens = (tp + EPSV) / (ts + EPSV);
        float cl = (2.f * tprec * tsens + EPSV) / (tprec + tsens + EPSV);
        acc += 1.f - cl;
    }
    out[0] = acc * 0.125f;
}

// ---------------- launch ----------------------------------------------------------
extern "C" void kernel_launch(void* const* d_in, const int* in_sizes, int n_in,
                              void* d_out, int out_size) {
    const float* logits = (const float*)d_in[0];
    const float* mask   = (const float*)d_in[1];
    const int*   cidx   = (const int*)d_in[2];
    float* out = (float*)d_out;

    prob_kernel<<<(NB * NPIX / 4 + 255) / 256, 256>>>(logits, mask, cidx);

    int nblocks = (NIMG * WPI) / 8;   // 640 blocks of 8 warps
    stage_kernel<<<nblocks, 256>>>(0, 1, 1);        // stage 0: src=prob, init skel
    int src = 1;
    for (int t = 1; t < ITERS; t++) {
        int dst = (src == 1) ? 2 : 1;
        int flags = (t == ITERS - 1) ? 2 : 0;
        stage_kernel<<<nblocks, 256>>>(src, dst, flags);
        src = dst;
    }

    reduce_kernel<<<256, 256>>>();
    final_kernel<<<1, 1>>>(out);
}

// round 4
// speedup vs baseline: 4.4014x; 1.3619x over previous
#include <cuda_runtime.h>
#include <cuda_bf16.h>
#include <cstdint>

#define NB   8
#define NC   19
#define HW   512
#define NPIX (HW*HW)
#define NIMG 16
#define ITERS 25
#define BIG  1e30f

// per-warp tile geometry
#define OUTW 120
#define NSX  5
#define ROWS 8
#define NSY  (HW/ROWS)      // 64
#define WPI  (NSX*NSY)      // 320 warps per image

__device__ float g_prob[NIMG * NPIX];
__device__ float g_imA [NIMG * NPIX];
__device__ float g_imB [NIMG * NPIX];
__device__ float g_skel[NIMG * NPIX];
__device__ float g_partials[512];

// ---------------- kernel 1: softmax class-prob + teacher clip (float4) ----------
__global__ void prob_kernel(const float* __restrict__ logits,
                            const float* __restrict__ mask,
                            const int* __restrict__ cidx) {
    int t = blockIdx.x * blockDim.x + threadIdx.x;
    if (t >= NB * NPIX / 4) return;
    int b = t >> 16;
    int p = (t & 65535) << 2;
    const float* lp = logits + (size_t)b * NC * NPIX + p;

    float4 v[NC];
    #pragma unroll
    for (int c = 0; c < NC; c++) v[c] = *(const float4*)(lp + (size_t)c * NPIX);

    float4 m = v[0];
    #pragma unroll
    for (int c = 1; c < NC; c++) {
        m.x = fmaxf(m.x, v[c].x); m.y = fmaxf(m.y, v[c].y);
        m.z = fmaxf(m.z, v[c].z); m.w = fmaxf(m.w, v[c].w);
    }
    int ci = *cidx;
    float4 s = {0,0,0,0}, tg = {0,0,0,0};
    #pragma unroll
    for (int c = 0; c < NC; c++) {
        float4 e;
        e.x = __expf(v[c].x - m.x); e.y = __expf(v[c].y - m.y);
        e.z = __expf(v[c].z - m.z); e.w = __expf(v[c].w - m.w);
        s.x += e.x; s.y += e.y; s.z += e.z; s.w += e.w;
        if (c == ci) tg = e;
    }
    float4 pr;
    pr.x = fminf(fmaxf(tg.x / s.x, 0.f), 1.f);
    pr.y = fminf(fmaxf(tg.y / s.y, 0.f), 1.f);
    pr.z = fminf(fmaxf(tg.z / s.z, 0.f), 1.f);
    pr.w = fminf(fmaxf(tg.w / s.w, 0.f), 1.f);
    *(float4*)(g_prob + b * NPIX + p) = pr;

    float4 mk = *(const float4*)(mask + b * NPIX + p);
    mk.x = fminf(fmaxf(mk.x, 0.f), 1.f);
    mk.y = fminf(fmaxf(mk.y, 0.f), 1.f);
    mk.z = fminf(fmaxf(mk.z, 0.f), 1.f);
    mk.w = fminf(fmaxf(mk.w, 0.f), 1.f);
    *(float4*)(g_prob + (NB + b) * NPIX + p) = mk;
}

// ---------------- morphology primitives -------------------------------------------
__device__ __forceinline__ float4 ldrow(const float* __restrict__ b, int q, int gx, bool ok) {
    if (ok && (unsigned)q < HW) return *(const float4*)(b + q * HW + gx);
    float4 r; r.x = r.y = r.z = r.w = BIG; return r;
}

// pure 3x3 erode of three rows (already carrying +BIG padding where invalid)
__device__ __forceinline__ float4 ero3(float4 a, float4 b, float4 c) {
    float4 v;
    v.x = fminf(fminf(a.x, b.x), c.x);
    v.y = fminf(fminf(a.y, b.y), c.y);
    v.z = fminf(fminf(a.z, b.z), c.z);
    v.w = fminf(fminf(a.w, b.w), c.w);
    float vl = __shfl_up_sync(0xFFFFFFFFu, v.w, 1);
    float vr = __shfl_down_sync(0xFFFFFFFFu, v.x, 1);
    float m01 = fminf(v.x, v.y), m12 = fminf(v.y, v.z), m23 = fminf(v.z, v.w);
    float4 e;
    e.x = fminf(vl, m01);
    e.y = fminf(m01, v.z);
    e.z = fminf(m12, v.w);
    e.w = fminf(m23, vr);
    return e;
}

// pure 3x3 dilate of three rows (already carrying -BIG padding where invalid)
__device__ __forceinline__ float4 dil3(float4 a, float4 b, float4 c) {
    float4 t;
    t.x = fmaxf(fmaxf(a.x, b.x), c.x);
    t.y = fmaxf(fmaxf(a.y, b.y), c.y);
    t.z = fmaxf(fmaxf(a.z, b.z), c.z);
    t.w = fmaxf(fmaxf(a.w, b.w), c.w);
    float tl = __shfl_up_sync(0xFFFFFFFFu, t.w, 1);
    float tr = __shfl_down_sync(0xFFFFFFFFu, t.x, 1);
    float M01 = fmaxf(t.x, t.y), M12 = fmaxf(t.y, t.z), M23 = fmaxf(t.z, t.w);
    float4 d;
    d.x = fmaxf(tl, M01);
    d.y = fmaxf(M01, t.z);
    d.z = fmaxf(M12, t.w);
    d.w = fmaxf(M23, tr);
    return d;
}

// select: inside -> v, outside -> pad
__device__ __forceinline__ float4 msel(float4 v, bool in, float pad) {
    float4 r;
    r.x = in ? v.x : pad;
    r.y = in ? v.y : pad;
    r.z = in ? v.z : pad;
    r.w = in ? v.w : pad;
    return r;
}

// ---------------- kernel 2: fused DOUBLE stage -------------------------------------
// stages (t, t+1): E1=erode(im); da=relu(im-dilate(E1)); skel upd;
//                  E2=erode(E1); db=relu(E1-dilate(E2)); skel upd; im_out=E2
__global__ void __launch_bounds__(256) fused_kernel(int srcsel, int dstsel, int init) {
    int w    = (blockIdx.x << 3) + (threadIdx.x >> 5);
    int lane = threadIdx.x & 31;
    int img  = w / WPI;
    int rem  = w - img * WPI;
    int sx   = rem / NSY;
    int sy   = rem - sx * NSY;
    int x0   = sx * OUTW;
    int r0   = sy * ROWS;
    int gx   = x0 - 4 + (lane << 2);

    bool colIn = (gx >= 0) && (gx < HW);
    bool stl   = (gx >= x0) && (gx < x0 + OUTW) && (gx < HW);

    const float* __restrict__ base =
        ((srcsel == 0) ? g_prob : (srcsel == 1 ? g_imA : g_imB)) + img * NPIX;
    float* __restrict__ outp = ((dstsel == 1) ? g_imA : g_imB) + img * NPIX;
    float* __restrict__ skp  = g_skel + img * NPIX;

    // ---- prologue: im rows r0-3..r0+3; E1 rows r0-2..r0+1; E2 rows r0-1..r0 ----
    float4 imm3 = ldrow(base, r0 - 3, gx, colIn);
    float4 imr[6];
    imr[4] = ldrow(base, r0 - 2, gx, colIn);
    imr[5] = ldrow(base, r0 - 1, gx, colIn);
    imr[0] = ldrow(base, r0 + 0, gx, colIn);
    imr[1] = ldrow(base, r0 + 1, gx, colIn);
    imr[2] = ldrow(base, r0 + 2, gx, colIn);
    imr[3] = ldrow(base, r0 + 3, gx, colIn);

    float4 e1[4], e2[3];
    float4 e1m2 = ero3(imm3, imr[4], imr[5]);                 // E1(r0-2) raw
    e1[3] = ero3(imr[4], imr[5], imr[0]);                      // E1(r0-1)
    e1[0] = ero3(imr[5], imr[0], imr[1]);                      // E1(r0)
    e1[1] = ero3(imr[0], imr[1], imr[2]);                      // E1(r0+1)

    {   // E2(r0-1), E2(r0) from +BIG-masked E1
        bool inA = colIn && ((unsigned)(r0 - 2) < HW);
        bool inB = colIn && ((unsigned)(r0 - 1) < HW);
        bool inC = colIn;  // r0 always in [0,HW)
        bool inD = colIn;  // r0+1 < HW (r0 <= 504)
        e2[2] = ero3(msel(e1m2, inA, BIG), msel(e1[3], inB, BIG), msel(e1[0], inC, BIG));
        e2[0] = ero3(msel(e1[3], inB, BIG), msel(e1[0], inC, BIG), msel(e1[1], inD, BIG));
    }

    #pragma unroll
    for (int i = 0; i < ROWS; i++) {
        int r = r0 + i;
        // prefetch im(r+4) -> slot (i+4)%6 (row r-2 is dead)
        imr[(i + 4) % 6] = ldrow(base, r + 4, gx, colIn);

        int o = r * HW + gx;
        float4 s;
        if (stl && !init) s = *(const float4*)(skp + o);

        // row-validity predicates (warp-uniform except colIn)
        bool inRm1 = colIn && ((unsigned)(r - 1) < HW);
        bool inR   = colIn;                         // r in [r0, r0+7] subset [0,511]
        bool inRp1 = colIn && ((unsigned)(r + 1) < HW);
        bool inRp2 = colIn && ((unsigned)(r + 2) < HW);

        // E1(r+2) raw from im rows r+1..r+3
        e1[(i + 2) % 4] = ero3(imr[(i + 1) % 6], imr[(i + 2) % 6], imr[(i + 3) % 6]);

        // E2(r+1) from +BIG-masked E1 rows r..r+2
        e2[(i + 1) % 3] = ero3(msel(e1[i % 4],       inR,   BIG),
                               msel(e1[(i + 1) % 4], inRp1, BIG),
                               msel(e1[(i + 2) % 4], inRp2, BIG));

        // D1(r) from -BIG-masked E1 rows r-1..r+1
        float4 d1 = dil3(msel(e1[(i + 3) % 4], inRm1, -BIG),
                         msel(e1[i % 4],       inR,   -BIG),
                         msel(e1[(i + 1) % 4], inRp1, -BIG));

        // D2(r) from -BIG-masked E2 rows r-1..r+1
        float4 d2 = dil3(msel(e2[(i + 2) % 3], inRm1, -BIG),
                         msel(e2[i % 3],       inR,   -BIG),
                         msel(e2[(i + 1) % 3], inRp1, -BIG));

        float4 ia = imr[i % 6];        // im(r)
        float4 da, db;
        da.x = fmaxf(ia.x - d1.x, 0.f);
        da.y = fmaxf(ia.y - d1.y, 0.f);
        da.z = fmaxf(ia.z - d1.z, 0.f);
        da.w = fmaxf(ia.w - d1.w, 0.f);
        float4 eb = e1[i % 4];         // E1(r) = im after stage A
        db.x = fmaxf(eb.x - d2.x, 0.f);
        db.y = fmaxf(eb.y - d2.y, 0.f);
        db.z = fmaxf(eb.z - d2.z, 0.f);
        db.w = fmaxf(eb.w - d2.w, 0.f);

        if (stl) {
            if (init) {
                s = da;
            } else {
                s.x += fmaxf(da.x - s.x * da.x, 0.f);
                s.y += fmaxf(da.y - s.y * da.y, 0.f);
                s.z += fmaxf(da.z - s.z * da.z, 0.f);
                s.w += fmaxf(da.w - s.w * da.w, 0.f);
            }
            s.x += fmaxf(db.x - s.x * db.x, 0.f);
            s.y += fmaxf(db.y - s.y * db.y, 0.f);
            s.z += fmaxf(db.z - s.z * db.z, 0.f);
            s.w += fmaxf(db.w - s.w * db.w, 0.f);
            *(float4*)(skp + o)  = s;
            *(float4*)(outp + o) = e2[i % 3];   // E2(r) = im after both stages
        }
    }
}

// ---------------- kernel 2b: single light stage (final, no im store) --------------
__global__ void __launch_bounds__(256) stage_kernel(int srcsel) {
    int w    = (blockIdx.x << 3) + (threadIdx.x >> 5);
    int lane = threadIdx.x & 31;
    int img  = w / WPI;
    int rem  = w - img * WPI;
    int sx   = rem / NSY;
    int sy   = rem - sx * NSY;
    int x0   = sx * OUTW;
    int r0   = sy * ROWS;
    int gx   = x0 - 4 + (lane << 2);

    bool colIn = (gx >= 0) && (gx < HW);
    bool stl   = (gx >= x0) && (gx < x0 + OUTW) && (gx < HW);

    const float* __restrict__ base = ((srcsel == 1) ? g_imA : g_imB) + img * NPIX;
    float* __restrict__ skp = g_skel + img * NPIX;

    float4 ring[6];
    #pragma unroll
    for (int j = 0; j < 6; j++) ring[j] = ldrow(base, r0 - 2 + j, gx, colIn);

    bool inM1 = colIn && ((unsigned)(r0 - 1) < HW);
    float4 Eprev = msel(ero3(ring[0], ring[1], ring[2]), inM1, -BIG);
    float4 Ecur  = msel(ero3(ring[1], ring[2], ring[3]), colIn, -BIG);

    #pragma unroll
    for (int i = 0; i < ROWS; i++) {
        int r = r0 + i;
        ring[i % 6] = ldrow(base, r + 4, gx, colIn);
        float4 s;
        int o = r * HW + gx;
        if (stl) s = *(const float4*)(skp + o);

        bool inP1 = colIn && ((unsigned)(r + 1) < HW);
        float4 En = msel(ero3(ring[(i + 2) % 6], ring[(i + 3) % 6], ring[(i + 4) % 6]),
                         inP1, -BIG);
        float4 dd = dil3(Eprev, Ecur, En);
        float4 ic = ring[(i + 2) % 6];
        float4 delta;
        delta.x = fmaxf(ic.x - dd.x, 0.f);
        delta.y = fmaxf(ic.y - dd.y, 0.f);
        delta.z = fmaxf(ic.z - dd.z, 0.f);
        delta.w = fmaxf(ic.w - dd.w, 0.f);

        if (stl) {
            s.x += fmaxf(delta.x - s.x * delta.x, 0.f);
            s.y += fmaxf(delta.y - s.y * delta.y, 0.f);
            s.z += fmaxf(delta.z - s.z * delta.z, 0.f);
            s.w += fmaxf(delta.w - s.w * delta.w, 0.f);
            *(float4*)(skp + o) = s;
        }
        Eprev = Ecur; Ecur = En;
    }
}

// ---------------- kernel 3: deterministic block-partial reduction ----------------
__global__ void reduce_kernel() {
    int img   = blockIdx.x >> 4;
    int chunk = blockIdx.x & 15;
    int pair  = img ^ 8;
    const float* sk = g_skel + img  * NPIX + chunk * 16384;
    const float* pp = g_prob + pair * NPIX + chunk * 16384;

    float s0 = 0.f, s1 = 0.f;
    for (int i = threadIdx.x * 4; i < 16384; i += 1024) {
        float4 a = *(const float4*)(sk + i);
        float4 b = *(const float4*)(pp + i);
        s0 += a.x * b.x + a.y * b.y + a.z * b.z + a.w * b.w;
        s1 += a.x + a.y + a.z + a.w;
    }
    #pragma unroll
    for (int o = 16; o > 0; o >>= 1) {
        s0 += __shfl_down_sync(0xFFFFFFFFu, s0, o);
        s1 += __shfl_down_sync(0xFFFFFFFFu, s1, o);
    }
    __shared__ float sh[64];
    int wp = threadIdx.x >> 5;
    if ((threadIdx.x & 31) == 0) { sh[wp] = s0; sh[32 + wp] = s1; }
    __syncthreads();
    if (threadIdx.x == 0) {
        float a = 0.f, b = 0.f;
        #pragma unroll
        for (int i = 0; i < 8; i++) { a += sh[i]; b += sh[32 + i]; }
        g_partials[blockIdx.x * 2]     = a;
        g_partials[blockIdx.x * 2 + 1] = b;
    }
}

// ---------------- kernel 4: final clDice scalar ----------------------------------
__global__ void final_kernel(float* __restrict__ out) {
    const float EPSV = 1e-6f;
    float acc = 0.f;
    for (int b = 0; b < NB; b++) {
        float sp = 0.f, ss = 0.f, tp = 0.f, ts = 0.f;
        for (int c = 0; c < 16; c++) {
            sp += g_partials[(b * 16 + c) * 2];
            ss += g_partials[(b * 16 + c) * 2 + 1];
            tp += g_partials[((b + 8) * 16 + c) * 2];
            ts += g_partials[((b + 8) * 16 + c) * 2 + 1];
        }
        float tprec = (sp + EPSV) / (ss + EPSV);
        float tsens = (tp + EPSV) / (ts + EPSV);
        float cl = (2.f * tprec * tsens + EPSV) / (tprec + tsens + EPSV);
        acc += 1.f - cl;
    }
    out[0] = acc * 0.125f;
}

// ---------------- launch ----------------------------------------------------------
extern "C" void kernel_launch(void* const* d_in, const int* in_sizes, int n_in,
                              void* d_out, int out_size) {
    const float* logits = (const float*)d_in[0];
    const float* mask   = (const float*)d_in[1];
    const int*   cidx   = (const int*)d_in[2];
    float* out = (float*)d_out;

    prob_kernel<<<(NB * NPIX / 4 + 255) / 256, 256>>>(logits, mask, cidx);

    int nblocks = (NIMG * WPI) / 8;                 // 640 blocks of 8 warps

    // stages 0..23: 12 fused double-stages
    fused_kernel<<<nblocks, 256>>>(0, 1, 1);        // stages 0,1 (init)
    int src = 1;
    for (int k = 1; k < 12; k++) {
        int dst = (src == 1) ? 2 : 1;
        fused_kernel<<<nblocks, 256>>>(src, dst, 0);
        src = dst;
    }
    // stage 24: single light stage, skel update only
    stage_kernel<<<nblocks, 256>>>(src);

    reduce_kernel<<<256, 256>>>();
    final_kernel<<<1, 1>>>(out);
}

// round 5
// speedup vs baseline: 4.4892x; 1.0200x over previous
#include <cuda_runtime.h>
#include <cuda_bf16.h>
#include <cstdint>

#define NB   8
#define NC   19
#define HW   512
#define NPIX (HW*HW)
#define NIMG 16
#define ITERS 25
#define BIG  1e30f

#define OUTW 120
#define NSX  5
#define ROWS 8
#define NSY  (HW/ROWS)      // 64
#define WPI  (NSX*NSY)      // 320 warps per image

__device__ float g_prob[NIMG * NPIX];
__device__ float g_imA [NIMG * NPIX];
__device__ float g_imB [NIMG * NPIX];
__device__ float g_skel[NIMG * NPIX];
__device__ float g_partials[512];

// ---------------- kernel 1: softmax class-prob + teacher clip (float4) ----------
__global__ void prob_kernel(const float* __restrict__ logits,
                            const float* __restrict__ mask,
                            const int* __restrict__ cidx) {
    int t = blockIdx.x * blockDim.x + threadIdx.x;
    if (t >= NB * NPIX / 4) return;
    int b = t >> 16;
    int p = (t & 65535) << 2;
    const float* lp = logits + (size_t)b * NC * NPIX + p;

    float4 v[NC];
    #pragma unroll
    for (int c = 0; c < NC; c++) v[c] = *(const float4*)(lp + (size_t)c * NPIX);

    float4 m = v[0];
    #pragma unroll
    for (int c = 1; c < NC; c++) {
        m.x = fmaxf(m.x, v[c].x); m.y = fmaxf(m.y, v[c].y);
        m.z = fmaxf(m.z, v[c].z); m.w = fmaxf(m.w, v[c].w);
    }
    int ci = *cidx;
    float4 s = {0,0,0,0}, tg = {0,0,0,0};
    #pragma unroll
    for (int c = 0; c < NC; c++) {
        float4 e;
        e.x = __expf(v[c].x - m.x); e.y = __expf(v[c].y - m.y);
        e.z = __expf(v[c].z - m.z); e.w = __expf(v[c].w - m.w);
        s.x += e.x; s.y += e.y; s.z += e.z; s.w += e.w;
        if (c == ci) tg = e;
    }
    float4 pr;
    pr.x = fminf(fmaxf(tg.x / s.x, 0.f), 1.f);
    pr.y = fminf(fmaxf(tg.y / s.y, 0.f), 1.f);
    pr.z = fminf(fmaxf(tg.z / s.z, 0.f), 1.f);
    pr.w = fminf(fmaxf(tg.w / s.w, 0.f), 1.f);
    *(float4*)(g_prob + b * NPIX + p) = pr;

    float4 mk = *(const float4*)(mask + b * NPIX + p);
    mk.x = fminf(fmaxf(mk.x, 0.f), 1.f);
    mk.y = fminf(fmaxf(mk.y, 0.f), 1.f);
    mk.z = fminf(fmaxf(mk.z, 0.f), 1.f);
    mk.w = fminf(fmaxf(mk.w, 0.f), 1.f);
    *(float4*)(g_prob + (NB + b) * NPIX + p) = mk;
}

// ---------------- morphology primitives -------------------------------------------
__device__ __forceinline__ float4 ldrow_e(const float* __restrict__ b, int q, int gx, bool ok) {
    if (ok && (unsigned)q < HW) return *(const float4*)(b + q * HW + gx);
    float4 r; r.x = r.y = r.z = r.w = BIG; return r;
}

template<bool EDGE>
__device__ __forceinline__ float4 ld(const float* __restrict__ b, int q, int gx, bool ok) {
    if (!EDGE) return *(const float4*)(b + q * HW + gx);
    return ldrow_e(b, q, gx, ok);
}

__device__ __forceinline__ float4 ero3(float4 a, float4 b, float4 c) {
    float4 v;
    v.x = fminf(fminf(a.x, b.x), c.x);
    v.y = fminf(fminf(a.y, b.y), c.y);
    v.z = fminf(fminf(a.z, b.z), c.z);
    v.w = fminf(fminf(a.w, b.w), c.w);
    float vl = __shfl_up_sync(0xFFFFFFFFu, v.w, 1);
    float vr = __shfl_down_sync(0xFFFFFFFFu, v.x, 1);
    float m01 = fminf(v.x, v.y), m12 = fminf(v.y, v.z), m23 = fminf(v.z, v.w);
    float4 e;
    e.x = fminf(vl, m01);
    e.y = fminf(m01, v.z);
    e.z = fminf(m12, v.w);
    e.w = fminf(m23, vr);
    return e;
}

__device__ __forceinline__ float4 dil3(float4 a, float4 b, float4 c) {
    float4 t;
    t.x = fmaxf(fmaxf(a.x, b.x), c.x);
    t.y = fmaxf(fmaxf(a.y, b.y), c.y);
    t.z = fmaxf(fmaxf(a.z, b.z), c.z);
    t.w = fmaxf(fmaxf(a.w, b.w), c.w);
    float tl = __shfl_up_sync(0xFFFFFFFFu, t.w, 1);
    float tr = __shfl_down_sync(0xFFFFFFFFu, t.x, 1);
    float M01 = fmaxf(t.x, t.y), M12 = fmaxf(t.y, t.z), M23 = fmaxf(t.z, t.w);
    float4 d;
    d.x = fmaxf(tl, M01);
    d.y = fmaxf(M01, t.z);
    d.z = fmaxf(M12, t.w);
    d.w = fmaxf(M23, tr);
    return d;
}

__device__ __forceinline__ float4 msel(float4 v, bool in, float pad) {
    float4 r;
    r.x = in ? v.x : pad;
    r.y = in ? v.y : pad;
    r.z = in ? v.z : pad;
    r.w = in ? v.w : pad;
    return r;
}

template<bool EDGE>
__device__ __forceinline__ float4 mk(float4 v, bool in, float pad) {
    if (!EDGE) return v;
    return msel(v, in, pad);
}

// ---------------- fused double-stage body ------------------------------------------
template<bool EDGE>
__device__ __forceinline__ void fused_body(
    const float* __restrict__ base, float* __restrict__ outp,
    float* __restrict__ skp, int r0, int gx, bool colIn, bool stl, bool init)
{
    float4 imm3 = ld<EDGE>(base, r0 - 3, gx, colIn);
    float4 imr[6];
    imr[4] = ld<EDGE>(base, r0 - 2, gx, colIn);
    imr[5] = ld<EDGE>(base, r0 - 1, gx, colIn);
    imr[0] = ld<EDGE>(base, r0 + 0, gx, colIn);
    imr[1] = ld<EDGE>(base, r0 + 1, gx, colIn);
    imr[2] = ld<EDGE>(base, r0 + 2, gx, colIn);
    imr[3] = ld<EDGE>(base, r0 + 3, gx, colIn);

    float4 e1[4], e2[3];
    float4 e1m2 = ero3(imm3, imr[4], imr[5]);
    e1[3] = ero3(imr[4], imr[5], imr[0]);
    e1[0] = ero3(imr[5], imr[0], imr[1]);
    e1[1] = ero3(imr[0], imr[1], imr[2]);

    {
        bool inA = colIn && ((unsigned)(r0 - 2) < HW);
        bool inB = colIn && ((unsigned)(r0 - 1) < HW);
        e2[2] = ero3(mk<EDGE>(e1m2, inA, BIG), mk<EDGE>(e1[3], inB, BIG),
                     mk<EDGE>(e1[0], colIn, BIG));
        e2[0] = ero3(mk<EDGE>(e1[3], inB, BIG), mk<EDGE>(e1[0], colIn, BIG),
                     mk<EDGE>(e1[1], colIn, BIG));
    }

    #pragma unroll
    for (int i = 0; i < ROWS; i++) {
        int r = r0 + i;
        imr[(i + 4) % 6] = ld<EDGE>(base, r + 4, gx, colIn);

        int o = r * HW + gx;
        float4 s;
        if (stl && !init) s = *(const float4*)(skp + o);

        bool inRm1 = colIn && ((unsigned)(r - 1) < HW);
        bool inRp1 = colIn && ((unsigned)(r + 1) < HW);
        bool inRp2 = colIn && ((unsigned)(r + 2) < HW);

        e1[(i + 2) % 4] = ero3(imr[(i + 1) % 6], imr[(i + 2) % 6], imr[(i + 3) % 6]);

        e2[(i + 1) % 3] = ero3(mk<EDGE>(e1[i % 4],       colIn, BIG),
                               mk<EDGE>(e1[(i + 1) % 4], inRp1, BIG),
                               mk<EDGE>(e1[(i + 2) % 4], inRp2, BIG));

        float4 d1 = dil3(mk<EDGE>(e1[(i + 3) % 4], inRm1, -BIG),
                         mk<EDGE>(e1[i % 4],       colIn, -BIG),
                         mk<EDGE>(e1[(i + 1) % 4], inRp1, -BIG));

        float4 d2 = dil3(mk<EDGE>(e2[(i + 2) % 3], inRm1, -BIG),
                         mk<EDGE>(e2[i % 3],       colIn, -BIG),
                         mk<EDGE>(e2[(i + 1) % 3], inRp1, -BIG));

        float4 ia = imr[i % 6];
        float4 da, db;
        da.x = fmaxf(ia.x - d1.x, 0.f);
        da.y = fmaxf(ia.y - d1.y, 0.f);
        da.z = fmaxf(ia.z - d1.z, 0.f);
        da.w = fmaxf(ia.w - d1.w, 0.f);
        float4 eb = e1[i % 4];
        db.x = fmaxf(eb.x - d2.x, 0.f);
        db.y = fmaxf(eb.y - d2.y, 0.f);
        db.z = fmaxf(eb.z - d2.z, 0.f);
        db.w = fmaxf(eb.w - d2.w, 0.f);

        if (stl) {
            if (init) {
                s = da;
            } else {
                s.x += fmaxf(da.x - s.x * da.x, 0.f);
                s.y += fmaxf(da.y - s.y * da.y, 0.f);
                s.z += fmaxf(da.z - s.z * da.z, 0.f);
                s.w += fmaxf(da.w - s.w * da.w, 0.f);
            }
            s.x += fmaxf(db.x - s.x * db.x, 0.f);
            s.y += fmaxf(db.y - s.y * db.y, 0.f);
            s.z += fmaxf(db.z - s.z * db.z, 0.f);
            s.w += fmaxf(db.w - s.w * db.w, 0.f);
            *(float4*)(skp + o)  = s;
            *(float4*)(outp + o) = e2[i % 3];
        }
    }
}

__global__ void __launch_bounds__(128, 6) fused_kernel(int srcsel, int dstsel, int init) {
    int w    = (blockIdx.x << 2) + (threadIdx.x >> 5);
    int lane = threadIdx.x & 31;
    int img  = w / WPI;
    int rem  = w - img * WPI;
    int sx   = rem / NSY;
    int sy   = rem - sx * NSY;
    int x0   = sx * OUTW;
    int r0   = sy * ROWS;
    int gx   = x0 - 4 + (lane << 2);

    bool colIn = (gx >= 0) && (gx < HW);
    bool stl   = (gx >= x0) && (gx < x0 + OUTW) && (gx < HW);

    const float* __restrict__ base =
        ((srcsel == 0) ? g_prob : (srcsel == 1 ? g_imA : g_imB)) + img * NPIX;
    float* __restrict__ outp = ((dstsel == 1) ? g_imA : g_imB) + img * NPIX;
    float* __restrict__ skp  = g_skel + img * NPIX;

    bool edge = (sx == 0) || (sx == NSX - 1) || (sy == 0) || (sy == NSY - 1);
    if (!edge) fused_body<false>(base, outp, skp, r0, gx, true,  stl, init != 0);
    else       fused_body<true >(base, outp, skp, r0, gx, colIn, stl, init != 0);
}

// ---------------- single light final stage ------------------------------------------
template<bool EDGE>
__device__ __forceinline__ void stage_body(
    const float* __restrict__ base, float* __restrict__ skp,
    int r0, int gx, bool colIn, bool stl)
{
    float4 ring[6];
    #pragma unroll
    for (int j = 0; j < 6; j++) ring[j] = ld<EDGE>(base, r0 - 2 + j, gx, colIn);

    bool inM1 = colIn && ((unsigned)(r0 - 1) < HW);
    float4 Eprev = mk<EDGE>(ero3(ring[0], ring[1], ring[2]), inM1, -BIG);
    float4 Ecur  = mk<EDGE>(ero3(ring[1], ring[2], ring[3]), colIn, -BIG);

    #pragma unroll
    for (int i = 0; i < ROWS; i++) {
        int r = r0 + i;
        ring[i % 6] = ld<EDGE>(base, r + 4, gx, colIn);
        float4 s;
        int o = r * HW + gx;
        if (stl) s = *(const float4*)(skp + o);

        bool inP1 = colIn && ((unsigned)(r + 1) < HW);
        float4 En = mk<EDGE>(ero3(ring[(i + 2) % 6], ring[(i + 3) % 6], ring[(i + 4) % 6]),
                             inP1, -BIG);
        float4 dd = dil3(Eprev, Ecur, En);
        float4 ic = ring[(i + 2) % 6];
        float4 delta;
        delta.x = fmaxf(ic.x - dd.x, 0.f);
        delta.y = fmaxf(ic.y - dd.y, 0.f);
        delta.z = fmaxf(ic.z - dd.z, 0.f);
        delta.w = fmaxf(ic.w - dd.w, 0.f);

        if (stl) {
            s.x += fmaxf(delta.x - s.x * delta.x, 0.f);
            s.y += fmaxf(delta.y - s.y * delta.y, 0.f);
            s.z += fmaxf(delta.z - s.z * delta.z, 0.f);
            s.w += fmaxf(delta.w - s.w * delta.w, 0.f);
            *(float4*)(skp + o) = s;
        }
        Eprev = Ecur; Ecur = En;
    }
}

__global__ void __launch_bounds__(128, 6) stage_kernel(int srcsel) {
    int w    = (blockIdx.x << 2) + (threadIdx.x >> 5);
    int lane = threadIdx.x & 31;
    int img  = w / WPI;
    int rem  = w - img * WPI;
    int sx   = rem / NSY;
    int sy   = rem - sx * NSY;
    int x0   = sx * OUTW;
    int r0   = sy * ROWS;
    int gx   = x0 - 4 + (lane << 2);

    bool colIn = (gx >= 0) && (gx < HW);
    bool stl   = (gx >= x0) && (gx < x0 + OUTW) && (gx < HW);

    const float* __restrict__ base = ((srcsel == 1) ? g_imA : g_imB) + img * NPIX;
    float* __restrict__ skp = g_skel + img * NPIX;

    bool edge = (sx == 0) || (sx == NSX - 1) || (sy == 0) || (sy == NSY - 1);
    if (!edge) stage_body<false>(base, skp, r0, gx, true,  stl);
    else       stage_body<true >(base, skp, r0, gx, colIn, stl);
}

// ---------------- kernel 3: deterministic block-partial reduction ----------------
__global__ void reduce_kernel() {
    int img   = blockIdx.x >> 4;
    int chunk = blockIdx.x & 15;
    int pair  = img ^ 8;
    const float* sk = g_skel + img  * NPIX + chunk * 16384;
    const float* pp = g_prob + pair * NPIX + chunk * 16384;

    float s0 = 0.f, s1 = 0.f;
    for (int i = threadIdx.x * 4; i < 16384; i += 1024) {
        float4 a = *(const float4*)(sk + i);
        float4 b = *(const float4*)(pp + i);
        s0 += a.x * b.x + a.y * b.y + a.z * b.z + a.w * b.w;
        s1 += a.x + a.y + a.z + a.w;
    }
    #pragma unroll
    for (int o = 16; o > 0; o >>= 1) {
        s0 += __shfl_down_sync(0xFFFFFFFFu, s0, o);
        s1 += __shfl_down_sync(0xFFFFFFFFu, s1, o);
    }
    __shared__ float sh[64];
    int wp = threadIdx.x >> 5;
    if ((threadIdx.x & 31) == 0) { sh[wp] = s0; sh[32 + wp] = s1; }
    __syncthreads();
    if (threadIdx.x == 0) {
        float a = 0.f, b = 0.f;
        #pragma unroll
        for (int i = 0; i < 8; i++) { a += sh[i]; b += sh[32 + i]; }
        g_partials[blockIdx.x * 2]     = a;
        g_partials[blockIdx.x * 2 + 1] = b;
    }
}

// ---------------- kernel 4: final clDice scalar ----------------------------------
__global__ void final_kernel(float* __restrict__ out) {
    const float EPSV = 1e-6f;
    float acc = 0.f;
    for (int b = 0; b < NB; b++) {
        float sp = 0.f, ss = 0.f, tp = 0.f, ts = 0.f;
        for (int c = 0; c < 16; c++) {
            sp += g_partials[(b * 16 + c) * 2];
            ss += g_partials[(b * 16 + c) * 2 + 1];
            tp += g_partials[((b + 8) * 16 + c) * 2];
            ts += g_partials[((b + 8) * 16 + c) * 2 + 1];
        }
        float tprec = (sp + EPSV) / (ss + EPSV);
        float tsens = (tp + EPSV) / (ts + EPSV);
        float cl = (2.f * tprec * tsens + EPSV) / (tprec + tsens + EPSV);
        acc += 1.f - cl;
    }
    out[0] = acc * 0.125f;
}

// ---------------- launch ----------------------------------------------------------
extern "C" void kernel_launch(void* const* d_in, const int* in_sizes, int n_in,
                              void* d_out, int out_size) {
    const float* logits = (const float*)d_in[0];
    const float* mask   = (const float*)d_in[1];
    const int*   cidx   = (const int*)d_in[2];
    float* out = (float*)d_out;

    prob_kernel<<<(NB * NPIX / 4 + 255) / 256, 256>>>(logits, mask, cidx);

    int nblocks = (NIMG * WPI) / 4;                 // 1280 blocks of 4 warps

    fused_kernel<<<nblocks, 128>>>(0, 1, 1);        // stages 0,1 (init)
    int src = 1;
    for (int k = 1; k < 12; k++) {
        int dst = (src == 1) ? 2 : 1;
        fused_kernel<<<nblocks, 128>>>(src, dst, 0);
        src = dst;
    }
    stage_kernel<<<nblocks, 128>>>(src);            // stage 24

    reduce_kernel<<<256, 256>>>();
    final_kernel<<<1, 1>>>(out);
}